// round 3
// baseline (speedup 1.0000x reference)
#include <cuda_runtime.h>

#define NSEQ   512
#define NBATCH 64
#define NHID   1024
#define NCAP   16
#define NDIM   64
#define NSPLIT 8
#define SCHUNK 64    // NSEQ / NSPLIT
#define NPART  16

typedef unsigned long long u64;

// Scratch (device globals — no allocation allowed)
__device__ float g_V[NBATCH * NCAP * NHID];                  // 4 MB
__device__ float g_Y[NBATCH * NSPLIT * NCAP * NHID];         // 32 MB
__device__ float g_opart[NPART * NBATCH * NCAP * NDIM];      // 4 MB
__device__ float g_O[NBATCH * NCAP * NDIM];                  // 256 KB

__device__ __forceinline__ void fma4(float4 &a, float4 x, float c) {
    a.x = fmaf(c, x.x, a.x);
    a.y = fmaf(c, x.y, a.y);
    a.z = fmaf(c, x.z, a.z);
    a.w = fmaf(c, x.w, a.w);
}
__device__ __forceinline__ u64 pack2(float lo, float hi) {
    u64 r; asm("mov.b64 %0, {%1, %2};" : "=l"(r) : "f"(lo), "f"(hi)); return r;
}
__device__ __forceinline__ void unpack2(u64 v, float &lo, float &hi) {
    asm("mov.b64 {%0, %1}, %2;" : "=f"(lo), "=f"(hi) : "l"(v));
}
__device__ __forceinline__ u64 ffma2(u64 a, u64 b, u64 c) {
    u64 d; asm("fma.rn.f32x2 %0, %1, %2, %3;" : "=l"(d) : "l"(a), "l"(b), "l"(c)); return d;
}
__device__ __forceinline__ u64 add2(u64 a, u64 b) {
    u64 d; asm("add.rn.f32x2 %0, %1, %2;" : "=l"(d) : "l"(a), "l"(b)); return d;
}
__device__ __forceinline__ u64 shfl_xor_u64(u64 v, int d) {
    unsigned lo = (unsigned)v, hi = (unsigned)(v >> 32);
    lo = __shfl_xor_sync(0xffffffffu, lo, d);
    hi = __shfl_xor_sync(0xffffffffu, hi, d);
    return ((u64)hi << 32) | (u64)lo;
}

// ---------------------------------------------------------------------------
// pass_kernel: CTA = (split of 64 s, batch b), 128 threads.
// smem: Vsh[16*1024] f32 (64KB) | cdup[64][16] u64 (8KB) | lsh[64*16] f32 (4KB)
// Stage A: logits l[s][nc] = x_s · V[nc] via h-paired ffma2, tile 4s x 8nc/warp.
// Softmax: 64 threads, one s each; writes duplicated (c,c) pairs.
// Stage B: Y[nc][h] += c[s][nc] * x[s][h] via h-paired ffma2 (c pre-duplicated).
// ---------------------------------------------------------------------------
__global__ void __launch_bounds__(128, 2)
pass_kernel(const float* __restrict__ X, int iter) {
    extern __shared__ float sm[];
    float* Vsh  = sm;                             // 16384 floats
    u64*   cdup = reinterpret_cast<u64*>(sm + 16384);  // 64*16 u64
    float* lsh  = sm + 16384 + 2048;              // 64*16 floats

    const int b     = blockIdx.y;
    const int split = blockIdx.x;
    const int t     = threadIdx.x;
    const int lane  = t & 31;
    const int w     = t >> 5;
    const int s0    = split * SCHUNK;
    const float4* X4 = reinterpret_cast<const float4*>(X);
    const size_t xrow = (size_t)NBATCH * (NHID / 4);   // float4 stride per s

    if (iter > 0) {
        // Load V[b] into shared
        const float4* Vb = reinterpret_cast<const float4*>(g_V) + (size_t)b * (NCAP * NHID / 4);
        float4* Vsh4 = reinterpret_cast<float4*>(Vsh);
        for (int i = t; i < NCAP * NHID / 4; i += 128) Vsh4[i] = Vb[i];
        __syncthreads();

        // ---- Stage A ----
        // warp w owns s-local [w*16, w*16+16), 4 chunks of 4 s.
        for (int chunk = 0; chunk < 4; ++chunk) {
            const int slBase = w * 16 + chunk * 4;
            const ulonglong2* xp0 = reinterpret_cast<const ulonglong2*>(X4 + ((size_t)(s0 + slBase + 0) * NBATCH + b) * (NHID / 4));
            const ulonglong2* xp1 = reinterpret_cast<const ulonglong2*>(X4 + ((size_t)(s0 + slBase + 1) * NBATCH + b) * (NHID / 4));
            const ulonglong2* xp2 = reinterpret_cast<const ulonglong2*>(X4 + ((size_t)(s0 + slBase + 2) * NBATCH + b) * (NHID / 4));
            const ulonglong2* xp3 = reinterpret_cast<const ulonglong2*>(X4 + ((size_t)(s0 + slBase + 3) * NBATCH + b) * (NHID / 4));

            #pragma unroll
            for (int half = 0; half < 2; ++half) {
                u64 acc[32];   // acc[s*8+nc], h-paired partial sums
                #pragma unroll
                for (int a = 0; a < 32; ++a) acc[a] = 0ull;

                const ulonglong2* V2 = reinterpret_cast<const ulonglong2*>(Vsh) + (size_t)half * 8 * 256;

                #pragma unroll
                for (int j = 0; j < 8; ++j) {
                    const int idx = lane + 32 * j;   // float4 index into the 1024-h row
                    ulonglong2 x0 = xp0[idx];
                    ulonglong2 x1 = xp1[idx];
                    ulonglong2 x2 = xp2[idx];
                    ulonglong2 x3 = xp3[idx];
                    #pragma unroll
                    for (int nc = 0; nc < 8; ++nc) {
                        ulonglong2 v = V2[nc * 256 + idx];
                        acc[0*8+nc] = ffma2(x0.x, v.x, acc[0*8+nc]);
                        acc[0*8+nc] = ffma2(x0.y, v.y, acc[0*8+nc]);
                        acc[1*8+nc] = ffma2(x1.x, v.x, acc[1*8+nc]);
                        acc[1*8+nc] = ffma2(x1.y, v.y, acc[1*8+nc]);
                        acc[2*8+nc] = ffma2(x2.x, v.x, acc[2*8+nc]);
                        acc[2*8+nc] = ffma2(x2.y, v.y, acc[2*8+nc]);
                        acc[3*8+nc] = ffma2(x3.x, v.x, acc[3*8+nc]);
                        acc[3*8+nc] = ffma2(x3.y, v.y, acc[3*8+nc]);
                    }
                }

                // Interleaved exchange-reduce: lane L ends with full sum of acc[L]
                #pragma unroll
                for (int d = 1; d < 32; d <<= 1) {
                    const bool upper = (lane & d) != 0;
                    #pragma unroll
                    for (int i = 0; i < 32; i += 2 * d) {
                        u64 mine  = upper ? acc[i] : acc[i + d];
                        u64 other = shfl_xor_u64(mine, d);
                        u64 keep  = upper ? acc[i + d] : acc[i];
                        acc[i] = add2(keep, other);
                    }
                }
                float lo, hi; unpack2(acc[0], lo, hi);
                const int sl = slBase + (lane >> 3);
                const int nc = half * 8 + (lane & 7);
                lsh[sl * 16 + nc] = lo + hi;
            }
        }
        __syncthreads();

        // ---- softmax over nc, write duplicated pairs ----
        if (t < SCHUNK) {
            float l[NCAP];
            #pragma unroll
            for (int i = 0; i < NCAP; ++i) l[i] = lsh[t * 16 + i];
            float m = l[0];
            #pragma unroll
            for (int i = 1; i < NCAP; ++i) m = fmaxf(m, l[i]);
            float e[NCAP]; float ssum = 0.f;
            #pragma unroll
            for (int i = 0; i < NCAP; ++i) { e[i] = __expf(l[i] - m); ssum += e[i]; }
            float inv = 1.0f / ssum;
            #pragma unroll
            for (int i = 0; i < NCAP; ++i) {
                float c = e[i] * inv;
                cdup[t * 16 + i] = pack2(c, c);
            }
        }
        __syncthreads();
    }

    // ---- Stage B ----  thread t owns 8 h (float4 indices t*2, t*2+1)
    float4* Y4 = reinterpret_cast<float4*>(g_Y) + (size_t)(b * NSPLIT + split) * (NCAP * NHID / 4);
    const ulonglong2* xb = reinterpret_cast<const ulonglong2*>(
        X4 + ((size_t)s0 * NBATCH + b) * (NHID / 4)) + t * 2;
    const size_t xrow2 = xrow / 2;  // ulonglong2 stride per s... (NHID/4 float4 = NHID/8 u2)

    if (iter == 0) {
        u64 a0 = 0ull, a1 = 0ull, a2 = 0ull, a3 = 0ull;
        for (int s = 0; s < SCHUNK; ++s) {
            ulonglong2 xa = xb[(size_t)s * (xrow / 2) * 2];      // careful: see below
            ulonglong2 xc = xb[(size_t)s * (xrow / 2) * 2 + 1];
            a0 = add2(a0, xa.x); a1 = add2(a1, xa.y);
            a2 = add2(a2, xc.x); a3 = add2(a3, xc.y);
        }
        float r[8];
        unpack2(a0, r[0], r[1]); unpack2(a1, r[2], r[3]);
        unpack2(a2, r[4], r[5]); unpack2(a3, r[6], r[7]);
        const float c = 1.0f / 16.0f;
        float4 f0 = make_float4(r[0]*c, r[1]*c, r[2]*c, r[3]*c);
        float4 f1 = make_float4(r[4]*c, r[5]*c, r[6]*c, r[7]*c);
        #pragma unroll
        for (int nc = 0; nc < NCAP; ++nc) {
            Y4[nc * 256 + t * 2]     = f0;
            Y4[nc * 256 + t * 2 + 1] = f1;
        }
    } else {
        u64 acc[NCAP][4];
        #pragma unroll
        for (int nc = 0; nc < NCAP; ++nc) {
            acc[nc][0] = 0ull; acc[nc][1] = 0ull; acc[nc][2] = 0ull; acc[nc][3] = 0ull;
        }
        const ulonglong2* cd2 = reinterpret_cast<const ulonglong2*>(cdup);
        for (int s = 0; s < SCHUNK; ++s) {
            ulonglong2 xa = xb[(size_t)s * (xrow / 2) * 2];
            ulonglong2 xc = xb[(size_t)s * (xrow / 2) * 2 + 1];
            #pragma unroll
            for (int k = 0; k < 8; ++k) {
                ulonglong2 cp = cd2[s * 8 + k];
                acc[2*k][0]   = ffma2(xa.x, cp.x, acc[2*k][0]);
                acc[2*k][1]   = ffma2(xa.y, cp.x, acc[2*k][1]);
                acc[2*k][2]   = ffma2(xc.x, cp.x, acc[2*k][2]);
                acc[2*k][3]   = ffma2(xc.y, cp.x, acc[2*k][3]);
                acc[2*k+1][0] = ffma2(xa.x, cp.y, acc[2*k+1][0]);
                acc[2*k+1][1] = ffma2(xa.y, cp.y, acc[2*k+1][1]);
                acc[2*k+1][2] = ffma2(xc.x, cp.y, acc[2*k+1][2]);
                acc[2*k+1][3] = ffma2(xc.y, cp.y, acc[2*k+1][3]);
            }
        }
        #pragma unroll
        for (int nc = 0; nc < NCAP; ++nc) {
            float4 f0, f1;
            unpack2(acc[nc][0], f0.x, f0.y); unpack2(acc[nc][1], f0.z, f0.w);
            unpack2(acc[nc][2], f1.x, f1.y); unpack2(acc[nc][3], f1.z, f1.w);
            Y4[nc * 256 + t * 2]     = f0;
            Y4[nc * 256 + t * 2 + 1] = f1;
        }
    }
}

// U1: opart[p][b][nc][dc] = sum_{hh in part} (sum_splits Y) * W
__global__ void __launch_bounds__(256)
u1_kernel(const float* __restrict__ W) {
    __shared__ float Wsh[64 * 64];
    __shared__ float ysh[64 * 65];

    const int nc = blockIdx.x;
    const int p  = blockIdx.y;
    const int h0 = p * 64;
    const int t  = threadIdx.x;

    #pragma unroll
    for (int k = 0; k < 16; ++k) {
        int idx = t + k * 256;
        int hh = idx >> 6, dc = idx & 63;
        Wsh[hh * 64 + dc] = W[(size_t)(h0 + hh) * (NCAP * NDIM) + nc * NDIM + dc];
    }
    #pragma unroll
    for (int k = 0; k < 16; ++k) {
        int idx = t + k * 256;
        int b = idx >> 6, hh = idx & 63;
        const float* yp = g_Y + (((size_t)b * NSPLIT) * NCAP + nc) * NHID + h0 + hh;
        float s = 0.f;
        #pragma unroll
        for (int sp = 0; sp < NSPLIT; ++sp) s += yp[(size_t)sp * NCAP * NHID];
        ysh[b * 65 + hh] = s;
    }
    __syncthreads();

    const int dc4  = (t & 15) * 4;
    const int brow = (t >> 4) * 4;
    float4 a0 = make_float4(0,0,0,0), a1 = a0, a2 = a0, a3 = a0;
    #pragma unroll 4
    for (int hh = 0; hh < 64; ++hh) {
        float4 w4 = *reinterpret_cast<const float4*>(&Wsh[hh * 64 + dc4]);
        fma4(a0, w4, ysh[(brow + 0) * 65 + hh]);
        fma4(a1, w4, ysh[(brow + 1) * 65 + hh]);
        fma4(a2, w4, ysh[(brow + 2) * 65 + hh]);
        fma4(a3, w4, ysh[(brow + 3) * 65 + hh]);
    }
    #pragma unroll
    for (int i = 0; i < 4; ++i) {
        float4 a = (i == 0) ? a0 : (i == 1) ? a1 : (i == 2) ? a2 : a3;
        *reinterpret_cast<float4*>(g_opart + (((size_t)p * NBATCH + brow + i) * NCAP + nc) * NDIM + dc4) = a;
    }
}

__global__ void __launch_bounds__(256)
squash_kernel(float* __restrict__ Og, int last) {
    const int b = blockIdx.x;
    const int t = threadIdx.x;
    const int nc = t >> 4;
    const int q  = t & 15;

    float4 a = make_float4(0,0,0,0);
    #pragma unroll
    for (int p = 0; p < NPART; ++p) {
        float4 v = *(reinterpret_cast<const float4*>(
            g_opart + (((size_t)p * NBATCH + b) * NCAP + nc) * NDIM) + q);
        a.x += v.x; a.y += v.y; a.z += v.z; a.w += v.w;
    }
    float ss = a.x * a.x + a.y * a.y + a.z * a.z + a.w * a.w;
    #pragma unroll
    for (int off = 8; off > 0; off >>= 1) ss += __shfl_xor_sync(0xffffffffu, ss, off);
    float inv = rsqrtf(ss + 1e-7f);
    a.x *= inv; a.y *= inv; a.z *= inv; a.w *= inv;

    *(reinterpret_cast<float4*>(g_O + ((size_t)b * NCAP + nc) * NDIM) + q) = a;
    if (last)
        *(reinterpret_cast<float4*>(Og + ((size_t)b * NCAP + nc) * NDIM) + q) = a;
}

__global__ void __launch_bounds__(256)
u2_kernel(const float* __restrict__ W, int iter) {
    __shared__ float WshT[64 * 68];
    __shared__ float osh[64 * 64];

    const int nc = blockIdx.x;
    const int p  = blockIdx.y;
    const int h0 = p * 64;
    const int t  = threadIdx.x;

    #pragma unroll
    for (int k = 0; k < 16; ++k) {
        int idx = t + k * 256;
        int hh = idx >> 6, dc = idx & 63;
        WshT[dc * 68 + hh] = W[(size_t)(h0 + hh) * (NCAP * NDIM) + nc * NDIM + dc];
    }
    #pragma unroll
    for (int k = 0; k < 16; ++k) {
        int idx = t + k * 256;
        int b = idx >> 6, dc = idx & 63;
        osh[b * 64 + dc] = g_O[((size_t)b * NCAP + nc) * NDIM + dc];
    }
    __syncthreads();

    const int hh4  = (t & 15) * 4;
    const int brow = (t >> 4) * 4;
    float4 a0 = make_float4(0,0,0,0), a1 = a0, a2 = a0, a3 = a0;
    #pragma unroll 4
    for (int dc = 0; dc < 64; ++dc) {
        float4 w4 = *reinterpret_cast<const float4*>(&WshT[dc * 68 + hh4]);
        fma4(a0, w4, osh[(brow + 0) * 64 + dc]);
        fma4(a1, w4, osh[(brow + 1) * 64 + dc]);
        fma4(a2, w4, osh[(brow + 2) * 64 + dc]);
        fma4(a3, w4, osh[(brow + 3) * 64 + dc]);
    }
    #pragma unroll
    for (int i = 0; i < 4; ++i) {
        float4 a = (i == 0) ? a0 : (i == 1) ? a1 : (i == 2) ? a2 : a3;
        float4* vp = reinterpret_cast<float4*>(
            g_V + (((size_t)(brow + i)) * NCAP + nc) * NHID + h0 + hh4);
        if (iter == 0) {
            *vp = a;
        } else {
            float4 old = *vp;
            old.x += a.x; old.y += a.y; old.z += a.z; old.w += a.w;
            *vp = old;
        }
    }
}

extern "C" void kernel_launch(void* const* d_in, const int* in_sizes, int n_in,
                              void* d_out, int out_size) {
    (void)n_in; (void)out_size;
    const float* X = (const float*)d_in[0];
    const float* W = (const float*)d_in[1];
    if (in_sizes[0] == NHID * NCAP * NDIM) { const float* tmp = X; X = W; W = tmp; }

    cudaFuncSetAttribute(pass_kernel, cudaFuncAttributeMaxDynamicSharedMemorySize, 77824);

    float* out = (float*)d_out;
    for (int iter = 0; iter < 4; ++iter) {
        pass_kernel<<<dim3(NSPLIT, NBATCH), 128, 77824>>>(X, iter);
        u1_kernel<<<dim3(NCAP, NPART), 256>>>(W);
        squash_kernel<<<NBATCH, 256>>>(out, iter == 3 ? 1 : 0);
        if (iter < 3) u2_kernel<<<dim3(NCAP, NPART), 256>>>(W, iter);
    }
}

// round 4
// speedup vs baseline: 1.5555x; 1.5555x over previous
#include <cuda_runtime.h>

#define NSEQ   512
#define NBATCH 64
#define NHID   1024
#define NCAP   16
#define NDIM   64
#define NSPLIT 4
#define SCHUNK 128   // NSEQ / NSPLIT
#define NPART  16

typedef unsigned long long u64;

// Scratch (device globals — no allocation allowed)
__device__ float g_V[NBATCH * NCAP * NHID];                  // 4 MB
__device__ float g_Y[NBATCH * NSPLIT * NCAP * NHID];         // 16 MB
__device__ float g_opart[NPART * NBATCH * NCAP * NDIM];      // 4 MB
__device__ float g_O[NBATCH * NCAP * NDIM];                  // 256 KB

__device__ __forceinline__ float dot4(float4 a, float4 b) {
    return fmaf(a.x, b.x, fmaf(a.y, b.y, fmaf(a.z, b.z, a.w * b.w)));
}
__device__ __forceinline__ void fma4(float4 &a, float4 x, float c) {
    a.x = fmaf(c, x.x, a.x);
    a.y = fmaf(c, x.y, a.y);
    a.z = fmaf(c, x.z, a.z);
    a.w = fmaf(c, x.w, a.w);
}
__device__ __forceinline__ u64 pack2(float lo, float hi) {
    u64 r; asm("mov.b64 %0, {%1, %2};" : "=l"(r) : "f"(lo), "f"(hi)); return r;
}
__device__ __forceinline__ void unpack2(u64 v, float &lo, float &hi) {
    asm("mov.b64 {%0, %1}, %2;" : "=f"(lo), "=f"(hi) : "l"(v));
}
__device__ __forceinline__ u64 ffma2(u64 a, u64 b, u64 c) {
    u64 d; asm("fma.rn.f32x2 %0, %1, %2, %3;" : "=l"(d) : "l"(a), "l"(b), "l"(c)); return d;
}

// Softmax over 16 logits, store duplicated (c,c) u64 pairs (for f32x2 FMA).
__device__ __forceinline__ void softmax_store_dup(u64* dst, const float* l) {
    float m = l[0];
    #pragma unroll
    for (int i = 1; i < NCAP; ++i) m = fmaxf(m, l[i]);
    float e[NCAP];
    float s = 0.f;
    #pragma unroll
    for (int i = 0; i < NCAP; ++i) { e[i] = __expf(l[i] - m); s += e[i]; }
    float inv = 1.0f / s;
    #pragma unroll
    for (int i = 0; i < NCAP; ++i) { float c = e[i] * inv; dst[i] = pack2(c, c); }
}

// ---------------------------------------------------------------------------
// pass_kernel: CTA = (split of 128 s, batch b), 256 threads.
// smem: Vsh 64KB | cdup[128][16] u64 (16KB)
// Stage A (scalar FFMA, R2-proven): logits + softmax -> duplicated pairs.
// Stage B (f32x2 FFMA, zero packing): Y[nc][h] = sum_s c[s][nc] * x[s][h].
// iter==0: c = 1/16 exactly; only the nc=0 slice of Y is written.
// ---------------------------------------------------------------------------
__global__ void __launch_bounds__(256, 2)
pass_kernel(const float* __restrict__ X, int iter) {
    extern __shared__ float sm[];
    float4* Vsh  = reinterpret_cast<float4*>(sm);          // 16 x 256 float4 (64 KB)
    u64*    cdup = reinterpret_cast<u64*>(sm + NCAP * NHID); // 128 x 16 u64 (16 KB)

    const int b     = blockIdx.y;
    const int split = blockIdx.x;
    const int t     = threadIdx.x;
    const int lane  = t & 31;
    const int w     = t >> 5;
    const int s0    = split * SCHUNK;
    const float4* X4 = reinterpret_cast<const float4*>(X);

    if (iter > 0) {
        // Load V[b] into shared (16K floats)
        const float4* Vb = reinterpret_cast<const float4*>(g_V) + (size_t)b * (NCAP * NHID / 4);
        for (int i = t; i < NCAP * NHID / 4; i += 256) Vsh[i] = Vb[i];
        __syncthreads();

        // Stage A: each warp handles 16 s-values, 4 at a time.
        for (int q = 0; q < 4; ++q) {
            const int sl = w * 16 + q * 4;
            const float4* xp0 = X4 + ((size_t)(s0 + sl + 0) * NBATCH + b) * (NHID / 4);
            const float4* xp1 = X4 + ((size_t)(s0 + sl + 1) * NBATCH + b) * (NHID / 4);
            const float4* xp2 = X4 + ((size_t)(s0 + sl + 2) * NBATCH + b) * (NHID / 4);
            const float4* xp3 = X4 + ((size_t)(s0 + sl + 3) * NBATCH + b) * (NHID / 4);
            float l0[NCAP], l1[NCAP], l2[NCAP], l3[NCAP];
            #pragma unroll
            for (int nc = 0; nc < NCAP; ++nc) { l0[nc] = 0.f; l1[nc] = 0.f; l2[nc] = 0.f; l3[nc] = 0.f; }

            #pragma unroll 2
            for (int j = 0; j < 8; ++j) {
                const int idx = lane + 32 * j;
                float4 x0 = xp0[idx];
                float4 x1 = xp1[idx];
                float4 x2 = xp2[idx];
                float4 x3 = xp3[idx];
                #pragma unroll
                for (int nc = 0; nc < NCAP; ++nc) {
                    float4 v = Vsh[nc * 256 + idx];
                    l0[nc] += dot4(x0, v);
                    l1[nc] += dot4(x1, v);
                    l2[nc] += dot4(x2, v);
                    l3[nc] += dot4(x3, v);
                }
            }
            #pragma unroll
            for (int off = 16; off > 0; off >>= 1) {
                #pragma unroll
                for (int nc = 0; nc < NCAP; ++nc) {
                    l0[nc] += __shfl_xor_sync(0xffffffffu, l0[nc], off);
                    l1[nc] += __shfl_xor_sync(0xffffffffu, l1[nc], off);
                    l2[nc] += __shfl_xor_sync(0xffffffffu, l2[nc], off);
                    l3[nc] += __shfl_xor_sync(0xffffffffu, l3[nc], off);
                }
            }
            if (lane == 0) {
                softmax_store_dup(cdup + (size_t)(sl + 0) * NCAP, l0);
                softmax_store_dup(cdup + (size_t)(sl + 1) * NCAP, l1);
                softmax_store_dup(cdup + (size_t)(sl + 2) * NCAP, l2);
                softmax_store_dup(cdup + (size_t)(sl + 3) * NCAP, l3);
            }
        }
        __syncthreads();
    }

    // Stage B: thread t owns float4 column t (h in [4t, 4t+4) as 2 f32x2 pairs).
    float4* Y4 = reinterpret_cast<float4*>(g_Y) + (size_t)(b * NSPLIT + split) * (NCAP * NHID / 4);
    const ulonglong2* xb = reinterpret_cast<const ulonglong2*>(
        X4 + ((size_t)s0 * NBATCH + b) * (NHID / 4)) + t;
    const size_t xstride = (size_t)NBATCH * (NHID / 4);   // ulonglong2 == float4 stride

    if (iter == 0) {
        float4 a = make_float4(0.f, 0.f, 0.f, 0.f);
        const float4* xbf = X4 + ((size_t)s0 * NBATCH + b) * (NHID / 4) + t;
        for (int s = 0; s < SCHUNK; ++s) {
            float4 x = xbf[(size_t)s * xstride];
            a.x += x.x; a.y += x.y; a.z += x.z; a.w += x.w;
        }
        const float c = 1.0f / 16.0f;   // softmax of zeros over 16 capsules (exact)
        a.x *= c; a.y *= c; a.z *= c; a.w *= c;
        Y4[t] = a;   // only nc=0 slice; u1 redirects on iter 0
    } else {
        u64 acc[NCAP][2];
        #pragma unroll
        for (int nc = 0; nc < NCAP; ++nc) { acc[nc][0] = 0ull; acc[nc][1] = 0ull; }
        const ulonglong2* cd2 = reinterpret_cast<const ulonglong2*>(cdup);
        #pragma unroll 2
        for (int s = 0; s < SCHUNK; ++s) {
            ulonglong2 xv = xb[(size_t)s * xstride];
            #pragma unroll
            for (int k = 0; k < 8; ++k) {
                ulonglong2 cp = cd2[s * 8 + k];   // (c,c) for nc=2k and nc=2k+1
                acc[2*k][0]   = ffma2(xv.x, cp.x, acc[2*k][0]);
                acc[2*k][1]   = ffma2(xv.y, cp.x, acc[2*k][1]);
                acc[2*k+1][0] = ffma2(xv.x, cp.y, acc[2*k+1][0]);
                acc[2*k+1][1] = ffma2(xv.y, cp.y, acc[2*k+1][1]);
            }
        }
        #pragma unroll
        for (int nc = 0; nc < NCAP; ++nc) {
            float4 r;
            unpack2(acc[nc][0], r.x, r.y);
            unpack2(acc[nc][1], r.z, r.w);
            Y4[nc * 256 + t] = r;
        }
    }
}

// U1: opart[p][b][nc][dc] = sum_{hh in part} (sum_splits Y) * W
// iter==0: Y holds data only in the nc=0 slice (identical for all nc).
__global__ void __launch_bounds__(256)
u1_kernel(const float* __restrict__ W, int iter) {
    __shared__ float Wsh[64 * 64];
    __shared__ float ysh[64 * 65];

    const int nc = blockIdx.x;
    const int p  = blockIdx.y;
    const int h0 = p * 64;
    const int t  = threadIdx.x;
    const int ncY = (iter == 0) ? 0 : nc;

    #pragma unroll
    for (int k = 0; k < 16; ++k) {
        int idx = t + k * 256;
        int hh = idx >> 6, dc = idx & 63;
        Wsh[hh * 64 + dc] = W[(size_t)(h0 + hh) * (NCAP * NDIM) + nc * NDIM + dc];
    }
    #pragma unroll
    for (int k = 0; k < 16; ++k) {
        int idx = t + k * 256;
        int b = idx >> 6, hh = idx & 63;
        const float* yp = g_Y + (((size_t)b * NSPLIT) * NCAP + ncY) * NHID + h0 + hh;
        ysh[b * 65 + hh] = yp[0] + yp[NCAP * NHID] + yp[2 * NCAP * NHID] + yp[3 * NCAP * NHID];
    }
    __syncthreads();

    const int dc4  = (t & 15) * 4;
    const int brow = (t >> 4) * 4;
    float4 a0 = make_float4(0,0,0,0), a1 = a0, a2 = a0, a3 = a0;
    #pragma unroll 4
    for (int hh = 0; hh < 64; ++hh) {
        float4 w4 = *reinterpret_cast<const float4*>(&Wsh[hh * 64 + dc4]);
        fma4(a0, w4, ysh[(brow + 0) * 65 + hh]);
        fma4(a1, w4, ysh[(brow + 1) * 65 + hh]);
        fma4(a2, w4, ysh[(brow + 2) * 65 + hh]);
        fma4(a3, w4, ysh[(brow + 3) * 65 + hh]);
    }
    #pragma unroll
    for (int i = 0; i < 4; ++i) {
        float4 a = (i == 0) ? a0 : (i == 1) ? a1 : (i == 2) ? a2 : a3;
        *reinterpret_cast<float4*>(g_opart + (((size_t)p * NBATCH + brow + i) * NCAP + nc) * NDIM + dc4) = a;
    }
}

__global__ void __launch_bounds__(256)
squash_kernel(float* __restrict__ Og, int last) {
    const int b = blockIdx.x;
    const int t = threadIdx.x;
    const int nc = t >> 4;
    const int q  = t & 15;

    float4 a = make_float4(0,0,0,0);
    #pragma unroll
    for (int p = 0; p < NPART; ++p) {
        float4 v = *(reinterpret_cast<const float4*>(
            g_opart + (((size_t)p * NBATCH + b) * NCAP + nc) * NDIM) + q);
        a.x += v.x; a.y += v.y; a.z += v.z; a.w += v.w;
    }
    float ss = a.x * a.x + a.y * a.y + a.z * a.z + a.w * a.w;
    #pragma unroll
    for (int off = 8; off > 0; off >>= 1) ss += __shfl_xor_sync(0xffffffffu, ss, off);
    float inv = rsqrtf(ss + 1e-7f);
    a.x *= inv; a.y *= inv; a.z *= inv; a.w *= inv;

    *(reinterpret_cast<float4*>(g_O + ((size_t)b * NCAP + nc) * NDIM) + q) = a;
    if (last)
        *(reinterpret_cast<float4*>(Og + ((size_t)b * NCAP + nc) * NDIM) + q) = a;
}

__global__ void __launch_bounds__(256)
u2_kernel(const float* __restrict__ W, int iter) {
    __shared__ float WshT[64 * 68];
    __shared__ float osh[64 * 64];

    const int nc = blockIdx.x;
    const int p  = blockIdx.y;
    const int h0 = p * 64;
    const int t  = threadIdx.x;

    #pragma unroll
    for (int k = 0; k < 16; ++k) {
        int idx = t + k * 256;
        int hh = idx >> 6, dc = idx & 63;
        WshT[dc * 68 + hh] = W[(size_t)(h0 + hh) * (NCAP * NDIM) + nc * NDIM + dc];
    }
    #pragma unroll
    for (int k = 0; k < 16; ++k) {
        int idx = t + k * 256;
        int b = idx >> 6, dc = idx & 63;
        osh[b * 64 + dc] = g_O[((size_t)b * NCAP + nc) * NDIM + dc];
    }
    __syncthreads();

    const int hh4  = (t & 15) * 4;
    const int brow = (t >> 4) * 4;
    float4 a0 = make_float4(0,0,0,0), a1 = a0, a2 = a0, a3 = a0;
    #pragma unroll 4
    for (int dc = 0; dc < 64; ++dc) {
        float4 w4 = *reinterpret_cast<const float4*>(&WshT[dc * 68 + hh4]);
        fma4(a0, w4, osh[(brow + 0) * 64 + dc]);
        fma4(a1, w4, osh[(brow + 1) * 64 + dc]);
        fma4(a2, w4, osh[(brow + 2) * 64 + dc]);
        fma4(a3, w4, osh[(brow + 3) * 64 + dc]);
    }
    #pragma unroll
    for (int i = 0; i < 4; ++i) {
        float4 a = (i == 0) ? a0 : (i == 1) ? a1 : (i == 2) ? a2 : a3;
        float4* vp = reinterpret_cast<float4*>(
            g_V + (((size_t)(brow + i)) * NCAP + nc) * NHID + h0 + hh4);
        if (iter == 0) {
            *vp = a;
        } else {
            float4 old = *vp;
            old.x += a.x; old.y += a.y; old.z += a.z; old.w += a.w;
            *vp = old;
        }
    }
}

extern "C" void kernel_launch(void* const* d_in, const int* in_sizes, int n_in,
                              void* d_out, int out_size) {
    (void)n_in; (void)out_size;
    const float* X = (const float*)d_in[0];
    const float* W = (const float*)d_in[1];
    if (in_sizes[0] == NHID * NCAP * NDIM) { const float* tmp = X; X = W; W = tmp; }

    cudaFuncSetAttribute(pass_kernel, cudaFuncAttributeMaxDynamicSharedMemorySize, 81920);

    float* out = (float*)d_out;
    for (int iter = 0; iter < 4; ++iter) {
        pass_kernel<<<dim3(NSPLIT, NBATCH), 256, 81920>>>(X, iter);
        u1_kernel<<<dim3(NCAP, NPART), 256>>>(W, iter);
        squash_kernel<<<NBATCH, 256>>>(out, iter == 3 ? 1 : 0);
        if (iter < 3) u2_kernel<<<dim3(NCAP, NPART), 256>>>(W, iter);
    }
}

// round 5
// speedup vs baseline: 1.6130x; 1.0369x over previous
#include <cuda_runtime.h>

#define NSEQ   512
#define NBATCH 64
#define NHID   1024
#define NCAP   16
#define NDIM   64
#define NSPLIT 4
#define SCHUNK 128   // NSEQ / NSPLIT
#define NPART  32    // h-split for update GEMMs (1024/32)

// Scratch (device globals — no allocation allowed)
__device__ float g_V[NBATCH * NCAP * NHID];                  // 4 MB
__device__ float g_Y[NBATCH * NSPLIT * NCAP * NHID];         // 16 MB
__device__ float g_opart[NPART * NBATCH * NCAP * NDIM];      // 8 MB
__device__ float g_O[NBATCH * NCAP * NDIM];                  // 256 KB

__device__ __forceinline__ float dot4(float4 a, float4 b) {
    return fmaf(a.x, b.x, fmaf(a.y, b.y, fmaf(a.z, b.z, a.w * b.w)));
}
__device__ __forceinline__ void fma4(float4 &a, float4 x, float c) {
    a.x = fmaf(c, x.x, a.x);
    a.y = fmaf(c, x.y, a.y);
    a.z = fmaf(c, x.z, a.z);
    a.w = fmaf(c, x.w, a.w);
}

__device__ __forceinline__ void softmax_store(float* dst, const float* l) {
    float m = l[0];
    #pragma unroll
    for (int i = 1; i < NCAP; ++i) m = fmaxf(m, l[i]);
    float e[NCAP];
    float s = 0.f;
    #pragma unroll
    for (int i = 0; i < NCAP; ++i) { e[i] = __expf(l[i] - m); s += e[i]; }
    float inv = 1.0f / s;
    #pragma unroll
    for (int i = 0; i < NCAP; ++i) dst[i] = e[i] * inv;
}

// ---------------------------------------------------------------------------
// pass_kernel: CTA = (split of 128 s, batch b), 256 threads. smem 72KB.
// Stage A: logits l[s][nc] = x_s · V[nc]; softmax -> csh.
// Stage B: Y[nc][h] = sum_s c[s][nc] * x[s][h]  (scalar FFMA, R2-proven).
// iter==0: c = 1/16 exactly; only the nc=0 slice of Y is written.
// ---------------------------------------------------------------------------
__global__ void __launch_bounds__(256, 2)
pass_kernel(const float* __restrict__ X, int iter) {
    extern __shared__ float sm[];
    float4* Vsh = reinterpret_cast<float4*>(sm);   // 16 x 256 float4 (64 KB)
    float*  csh = sm + NCAP * NHID;                // 128 x 16 floats (8 KB)

    const int b     = blockIdx.y;
    const int split = blockIdx.x;
    const int t     = threadIdx.x;
    const int lane  = t & 31;
    const int w     = t >> 5;
    const int s0    = split * SCHUNK;
    const float4* X4 = reinterpret_cast<const float4*>(X);

    if (iter > 0) {
        const float4* Vb = reinterpret_cast<const float4*>(g_V) + (size_t)b * (NCAP * NHID / 4);
        for (int i = t; i < NCAP * NHID / 4; i += 256) Vsh[i] = Vb[i];
        __syncthreads();

        // Stage A: each warp handles 16 s-values, 4 at a time.
        for (int q = 0; q < 4; ++q) {
            const int sl = w * 16 + q * 4;
            const float4* xp0 = X4 + ((size_t)(s0 + sl + 0) * NBATCH + b) * (NHID / 4);
            const float4* xp1 = X4 + ((size_t)(s0 + sl + 1) * NBATCH + b) * (NHID / 4);
            const float4* xp2 = X4 + ((size_t)(s0 + sl + 2) * NBATCH + b) * (NHID / 4);
            const float4* xp3 = X4 + ((size_t)(s0 + sl + 3) * NBATCH + b) * (NHID / 4);
            float l0[NCAP], l1[NCAP], l2[NCAP], l3[NCAP];
            #pragma unroll
            for (int nc = 0; nc < NCAP; ++nc) { l0[nc] = 0.f; l1[nc] = 0.f; l2[nc] = 0.f; l3[nc] = 0.f; }

            #pragma unroll 2
            for (int j = 0; j < 8; ++j) {
                const int idx = lane + 32 * j;
                float4 x0 = xp0[idx];
                float4 x1 = xp1[idx];
                float4 x2 = xp2[idx];
                float4 x3 = xp3[idx];
                #pragma unroll
                for (int nc = 0; nc < NCAP; ++nc) {
                    float4 v = Vsh[nc * 256 + idx];
                    l0[nc] += dot4(x0, v);
                    l1[nc] += dot4(x1, v);
                    l2[nc] += dot4(x2, v);
                    l3[nc] += dot4(x3, v);
                }
            }
            #pragma unroll
            for (int off = 16; off > 0; off >>= 1) {
                #pragma unroll
                for (int nc = 0; nc < NCAP; ++nc) {
                    l0[nc] += __shfl_xor_sync(0xffffffffu, l0[nc], off);
                    l1[nc] += __shfl_xor_sync(0xffffffffu, l1[nc], off);
                    l2[nc] += __shfl_xor_sync(0xffffffffu, l2[nc], off);
                    l3[nc] += __shfl_xor_sync(0xffffffffu, l3[nc], off);
                }
            }
            if (lane == 0) {
                softmax_store(csh + (size_t)(sl + 0) * NCAP, l0);
                softmax_store(csh + (size_t)(sl + 1) * NCAP, l1);
                softmax_store(csh + (size_t)(sl + 2) * NCAP, l2);
                softmax_store(csh + (size_t)(sl + 3) * NCAP, l3);
            }
        }
        __syncthreads();
    }

    // Stage B: thread t owns float4 column t.
    float4* Y4 = reinterpret_cast<float4*>(g_Y) + (size_t)(b * NSPLIT + split) * (NCAP * NHID / 4);
    const float4* xb = X4 + ((size_t)s0 * NBATCH + b) * (NHID / 4) + t;
    const size_t xstride = (size_t)NBATCH * (NHID / 4);

    if (iter == 0) {
        float4 a = make_float4(0.f, 0.f, 0.f, 0.f);
        #pragma unroll 8
        for (int s = 0; s < SCHUNK; ++s) {
            float4 x = xb[(size_t)s * xstride];
            a.x += x.x; a.y += x.y; a.z += x.z; a.w += x.w;
        }
        const float c = 1.0f / 16.0f;   // softmax of zeros over 16 capsules (exact)
        a.x *= c; a.y *= c; a.z *= c; a.w *= c;
        Y4[t] = a;   // only nc=0 slice; u1 redirects on iter 0
    } else {
        float4 acc[NCAP];
        #pragma unroll
        for (int nc = 0; nc < NCAP; ++nc) acc[nc] = make_float4(0.f, 0.f, 0.f, 0.f);
        const float4* c4 = reinterpret_cast<const float4*>(csh);
        #pragma unroll 2
        for (int s = 0; s < SCHUNK; ++s) {
            float4 x = xb[(size_t)s * xstride];
            float4 ca = c4[s * 4 + 0];
            float4 cb = c4[s * 4 + 1];
            float4 cc = c4[s * 4 + 2];
            float4 cd = c4[s * 4 + 3];
            fma4(acc[0],  x, ca.x); fma4(acc[1],  x, ca.y); fma4(acc[2],  x, ca.z); fma4(acc[3],  x, ca.w);
            fma4(acc[4],  x, cb.x); fma4(acc[5],  x, cb.y); fma4(acc[6],  x, cb.z); fma4(acc[7],  x, cb.w);
            fma4(acc[8],  x, cc.x); fma4(acc[9],  x, cc.y); fma4(acc[10], x, cc.z); fma4(acc[11], x, cc.w);
            fma4(acc[12], x, cd.x); fma4(acc[13], x, cd.y); fma4(acc[14], x, cd.z); fma4(acc[15], x, cd.w);
        }
        #pragma unroll
        for (int nc = 0; nc < NCAP; ++nc) Y4[nc * 256 + t] = acc[nc];
    }
}

// U1: opart[p][b][nc][dc] = sum_{hh in 32-part} (sum_splits Y) * W
// iter==0: Y holds data only in the nc=0 slice (identical for all nc).
__global__ void __launch_bounds__(256)
u1_kernel(const float* __restrict__ W, int iter) {
    __shared__ float Wsh[32 * 64];   // [hh][dc]
    __shared__ float ysh[64 * 33];   // [b][hh], padded

    const int nc = blockIdx.x;
    const int p  = blockIdx.y;
    const int h0 = p * 32;
    const int t  = threadIdx.x;
    const int ncY = (iter == 0) ? 0 : nc;

    #pragma unroll
    for (int k = 0; k < 8; ++k) {
        int idx = t + k * 256;
        int hh = idx >> 6, dc = idx & 63;
        Wsh[hh * 64 + dc] = W[(size_t)(h0 + hh) * (NCAP * NDIM) + nc * NDIM + dc];
    }
    #pragma unroll
    for (int k = 0; k < 8; ++k) {
        int idx = t + k * 256;
        int b = idx >> 5, hh = idx & 31;
        const float* yp = g_Y + (((size_t)b * NSPLIT) * NCAP + ncY) * NHID + h0 + hh;
        ysh[b * 33 + hh] = yp[0] + yp[NCAP * NHID] + yp[2 * NCAP * NHID] + yp[3 * NCAP * NHID];
    }
    __syncthreads();

    const int dc4  = (t & 15) * 4;
    const int brow = (t >> 4) * 4;
    float4 a0 = make_float4(0,0,0,0), a1 = a0, a2 = a0, a3 = a0;
    #pragma unroll 8
    for (int hh = 0; hh < 32; ++hh) {
        float4 w4 = *reinterpret_cast<const float4*>(&Wsh[hh * 64 + dc4]);
        fma4(a0, w4, ysh[(brow + 0) * 33 + hh]);
        fma4(a1, w4, ysh[(brow + 1) * 33 + hh]);
        fma4(a2, w4, ysh[(brow + 2) * 33 + hh]);
        fma4(a3, w4, ysh[(brow + 3) * 33 + hh]);
    }
    #pragma unroll
    for (int i = 0; i < 4; ++i) {
        float4 a = (i == 0) ? a0 : (i == 1) ? a1 : (i == 2) ? a2 : a3;
        *reinterpret_cast<float4*>(g_opart + (((size_t)p * NBATCH + brow + i) * NCAP + nc) * NDIM + dc4) = a;
    }
}

__global__ void __launch_bounds__(256)
squash_kernel(float* __restrict__ Og, int last) {
    const int b = blockIdx.x;
    const int t = threadIdx.x;
    const int nc = t >> 4;
    const int q  = t & 15;

    float4 a = make_float4(0,0,0,0);
    #pragma unroll
    for (int p = 0; p < NPART; ++p) {
        float4 v = *(reinterpret_cast<const float4*>(
            g_opart + (((size_t)p * NBATCH + b) * NCAP + nc) * NDIM) + q);
        a.x += v.x; a.y += v.y; a.z += v.z; a.w += v.w;
    }
    float ss = a.x * a.x + a.y * a.y + a.z * a.z + a.w * a.w;
    #pragma unroll
    for (int off = 8; off > 0; off >>= 1) ss += __shfl_xor_sync(0xffffffffu, ss, off);
    float inv = rsqrtf(ss + 1e-7f);
    a.x *= inv; a.y *= inv; a.z *= inv; a.w *= inv;

    *(reinterpret_cast<float4*>(g_O + ((size_t)b * NCAP + nc) * NDIM) + q) = a;
    if (last)
        *(reinterpret_cast<float4*>(Og + ((size_t)b * NCAP + nc) * NDIM) + q) = a;
}

// U2: V[b][nc][h0+hh] (+)= sum_dc W[h0+hh][nc*64+dc] * o[b][nc][dc], 32-h tiles.
__global__ void __launch_bounds__(256)
u2_kernel(const float* __restrict__ W, int iter) {
    __shared__ float WshT[64 * 36];  // [dc][hh], padded
    __shared__ float osh[64 * 64];   // [b][dc]

    const int nc = blockIdx.x;
    const int p  = blockIdx.y;
    const int h0 = p * 32;
    const int t  = threadIdx.x;

    #pragma unroll
    for (int k = 0; k < 8; ++k) {
        int idx = t + k * 256;
        int hh = idx >> 6, dc = idx & 63;
        WshT[dc * 36 + hh] = W[(size_t)(h0 + hh) * (NCAP * NDIM) + nc * NDIM + dc];
    }
    #pragma unroll
    for (int k = 0; k < 16; ++k) {
        int idx = t + k * 256;
        int b = idx >> 6, dc = idx & 63;
        osh[b * 64 + dc] = g_O[((size_t)b * NCAP + nc) * NDIM + dc];
    }
    __syncthreads();

    const int hq = (t & 7) * 4;      // h-quad within the 32-h tile
    const int b0 = (t >> 3);         // 0..31; also handles b0+32
    float4 a0 = make_float4(0,0,0,0), a1 = a0;
    #pragma unroll 8
    for (int dc = 0; dc < 64; ++dc) {
        float4 w4 = *reinterpret_cast<const float4*>(&WshT[dc * 36 + hq]);
        fma4(a0, w4, osh[(b0)      * 64 + dc]);
        fma4(a1, w4, osh[(b0 + 32) * 64 + dc]);
    }
    float4* vp0 = reinterpret_cast<float4*>(g_V + ((size_t)b0        * NCAP + nc) * NHID + h0 + hq);
    float4* vp1 = reinterpret_cast<float4*>(g_V + ((size_t)(b0 + 32) * NCAP + nc) * NHID + h0 + hq);
    if (iter == 0) {
        *vp0 = a0; *vp1 = a1;
    } else {
        float4 o0 = *vp0, o1 = *vp1;
        o0.x += a0.x; o0.y += a0.y; o0.z += a0.z; o0.w += a0.w;
        o1.x += a1.x; o1.y += a1.y; o1.z += a1.z; o1.w += a1.w;
        *vp0 = o0; *vp1 = o1;
    }
}

extern "C" void kernel_launch(void* const* d_in, const int* in_sizes, int n_in,
                              void* d_out, int out_size) {
    (void)n_in; (void)out_size;
    const float* X = (const float*)d_in[0];
    const float* W = (const float*)d_in[1];
    if (in_sizes[0] == NHID * NCAP * NDIM) { const float* tmp = X; X = W; W = tmp; }

    cudaFuncSetAttribute(pass_kernel, cudaFuncAttributeMaxDynamicSharedMemorySize, 73728);

    float* out = (float*)d_out;
    for (int iter = 0; iter < 4; ++iter) {
        pass_kernel<<<dim3(NSPLIT, NBATCH), 256, 73728>>>(X, iter);
        u1_kernel<<<dim3(NCAP, NPART), 256>>>(W, iter);
        squash_kernel<<<NBATCH, 256>>>(out, iter == 3 ? 1 : 0);
        if (iter < 3) u2_kernel<<<dim3(NCAP, NPART), 256>>>(W, iter);
    }
}

// round 6
// speedup vs baseline: 1.7183x; 1.0653x over previous
#include <cuda_runtime.h>

#define NSEQ   512
#define NBATCH 64
#define NHID   1024
#define NCAP   16
#define NDIM   64
#define NSPLIT 4
#define SCHUNK 128   // NSEQ / NSPLIT
#define NPART  16    // h-split for update GEMMs (1024/64)

// Scratch (device globals — no allocation allowed)
__device__ float g_V[NBATCH * NCAP * NHID];                  // 4 MB
__device__ float g_Y[NBATCH * NSPLIT * NCAP * NHID];         // 16 MB
__device__ float g_opart[NPART * NBATCH * NCAP * NDIM];      // 4 MB
__device__ float g_O[NBATCH * NCAP * NDIM];                  // 256 KB

__device__ __forceinline__ float dot4(float4 a, float4 b) {
    return fmaf(a.x, b.x, fmaf(a.y, b.y, fmaf(a.z, b.z, a.w * b.w)));
}
__device__ __forceinline__ void fma4(float4 &a, float4 x, float c) {
    a.x = fmaf(c, x.x, a.x);
    a.y = fmaf(c, x.y, a.y);
    a.z = fmaf(c, x.z, a.z);
    a.w = fmaf(c, x.w, a.w);
}

// ---------------------------------------------------------------------------
// pass_kernel: CTA = (split of 128 s, batch b), 256 threads. smem 72KB.
// Stage A: logits l[s][nc] = x_s · V[nc], interleaved halving warp-reduce.
// Softmax: 128 threads, in-place in lsh.
// Stage B: Y[nc][h] = sum_s c[s][nc] * x[s][h]  (scalar FFMA, proven).
// iter==0: c = 1/16 exactly; only the nc=0 slice of Y is written.
// ---------------------------------------------------------------------------
__global__ void __launch_bounds__(256, 2)
pass_kernel(const float* __restrict__ X, int iter) {
    extern __shared__ float sm[];
    float4* Vsh = reinterpret_cast<float4*>(sm);   // 16 x 256 float4 (64 KB)
    float*  lsh = sm + NCAP * NHID;                // 128 x 16 floats (8 KB) — logits, then c

    const int b     = blockIdx.y;
    const int split = blockIdx.x;
    const int t     = threadIdx.x;
    const int lane  = t & 31;
    const int w     = t >> 5;
    const int s0    = split * SCHUNK;
    const float4* X4 = reinterpret_cast<const float4*>(X);

    if (iter > 0) {
        const float4* Vb = reinterpret_cast<const float4*>(g_V) + (size_t)b * (NCAP * NHID / 4);
        for (int i = t; i < NCAP * NHID / 4; i += 256) Vsh[i] = Vb[i];
        __syncthreads();

        // Stage A: each warp handles 16 s-values, 4 at a time.
        for (int q = 0; q < 4; ++q) {
            const int sl = w * 16 + q * 4;
            const float4* xp0 = X4 + ((size_t)(s0 + sl + 0) * NBATCH + b) * (NHID / 4);
            const float4* xp1 = X4 + ((size_t)(s0 + sl + 1) * NBATCH + b) * (NHID / 4);
            const float4* xp2 = X4 + ((size_t)(s0 + sl + 2) * NBATCH + b) * (NHID / 4);
            const float4* xp3 = X4 + ((size_t)(s0 + sl + 3) * NBATCH + b) * (NHID / 4);

            // v[idx], idx = s*16 + nc  (s in bits 5..4, nc in bits 3..0)
            float v[64];
            #pragma unroll
            for (int i = 0; i < 64; ++i) v[i] = 0.f;

            #pragma unroll 2
            for (int j = 0; j < 8; ++j) {
                const int idx = lane + 32 * j;
                float4 x0 = xp0[idx];
                float4 x1 = xp1[idx];
                float4 x2 = xp2[idx];
                float4 x3 = xp3[idx];
                #pragma unroll
                for (int nc = 0; nc < NCAP; ++nc) {
                    float4 vv = Vsh[nc * 256 + idx];
                    v[nc]      += dot4(x0, vv);
                    v[16 + nc] += dot4(x1, vv);
                    v[32 + nc] += dot4(x2, vv);
                    v[48 + nc] += dot4(x3, vv);
                }
            }

            // Interleaved halving reduce: level d retires half the array.
            // up-lane (bit d set) keeps+receives the UPPER half (top idx bit of
            // the current array); down-lane the lower half.
            #pragma unroll
            for (int step = 0; step < 5; ++step) {
                const int d = 1 << step;
                const int n = 64 >> step;
                const bool up = (lane & d) != 0;
                #pragma unroll
                for (int i = 0; i < n / 2; ++i) {
                    float send = up ? v[i] : v[i + n / 2];
                    float keep = up ? v[i + n / 2] : v[i];
                    v[i] = keep + __shfl_xor_sync(0xffffffffu, send, d);
                }
            }
            // lane L holds sums for idx = (L0<<5)|(L1<<4)|(L2<<3)|(L3<<2)|(L4<<1)|e
            const int sl_r = sl + (((lane & 1) << 1) | ((lane >> 1) & 1));
            const int nc_r = (((lane >> 2) & 1) << 3) | (((lane >> 3) & 1) << 2) | (((lane >> 4) & 1) << 1);
            lsh[sl_r * NCAP + nc_r]     = v[0];
            lsh[sl_r * NCAP + nc_r + 1] = v[1];
        }
        __syncthreads();

        // Softmax in-place: thread t (< 128) handles s-local t.
        if (t < SCHUNK) {
            float l[NCAP];
            #pragma unroll
            for (int i = 0; i < NCAP; ++i) l[i] = lsh[t * NCAP + i];
            float m = l[0];
            #pragma unroll
            for (int i = 1; i < NCAP; ++i) m = fmaxf(m, l[i]);
            float e[NCAP]; float ssum = 0.f;
            #pragma unroll
            for (int i = 0; i < NCAP; ++i) { e[i] = __expf(l[i] - m); ssum += e[i]; }
            float inv = 1.0f / ssum;
            #pragma unroll
            for (int i = 0; i < NCAP; ++i) lsh[t * NCAP + i] = e[i] * inv;
        }
        __syncthreads();
    }

    // Stage B: thread t owns float4 column t.
    float4* Y4 = reinterpret_cast<float4*>(g_Y) + (size_t)(b * NSPLIT + split) * (NCAP * NHID / 4);
    const float4* xb = X4 + ((size_t)s0 * NBATCH + b) * (NHID / 4) + t;
    const size_t xstride = (size_t)NBATCH * (NHID / 4);

    if (iter == 0) {
        float4 a = make_float4(0.f, 0.f, 0.f, 0.f);
        #pragma unroll 8
        for (int s = 0; s < SCHUNK; ++s) {
            float4 x = xb[(size_t)s * xstride];
            a.x += x.x; a.y += x.y; a.z += x.z; a.w += x.w;
        }
        const float c = 1.0f / 16.0f;   // softmax of zeros over 16 capsules (exact)
        a.x *= c; a.y *= c; a.z *= c; a.w *= c;
        Y4[t] = a;   // only nc=0 slice; u1 redirects on iter 0
    } else {
        float4 acc[NCAP];
        #pragma unroll
        for (int nc = 0; nc < NCAP; ++nc) acc[nc] = make_float4(0.f, 0.f, 0.f, 0.f);
        const float4* c4 = reinterpret_cast<const float4*>(lsh);
        #pragma unroll 2
        for (int s = 0; s < SCHUNK; ++s) {
            float4 x = xb[(size_t)s * xstride];
            float4 ca = c4[s * 4 + 0];
            float4 cb = c4[s * 4 + 1];
            float4 cc = c4[s * 4 + 2];
            float4 cd = c4[s * 4 + 3];
            fma4(acc[0],  x, ca.x); fma4(acc[1],  x, ca.y); fma4(acc[2],  x, ca.z); fma4(acc[3],  x, ca.w);
            fma4(acc[4],  x, cb.x); fma4(acc[5],  x, cb.y); fma4(acc[6],  x, cb.z); fma4(acc[7],  x, cb.w);
            fma4(acc[8],  x, cc.x); fma4(acc[9],  x, cc.y); fma4(acc[10], x, cc.z); fma4(acc[11], x, cc.w);
            fma4(acc[12], x, cd.x); fma4(acc[13], x, cd.y); fma4(acc[14], x, cd.z); fma4(acc[15], x, cd.w);
        }
        #pragma unroll
        for (int nc = 0; nc < NCAP; ++nc) Y4[nc * 256 + t] = acc[nc];
    }
}

// U1: opart[p][b][nc][dc] = sum_{hh in 64-part} (sum_splits Y) * W
// iter==0: Y holds data only in the nc=0 slice (identical for all nc).
__global__ void __launch_bounds__(256)
u1_kernel(const float* __restrict__ W, int iter) {
    __shared__ float Wsh[64 * 64];
    __shared__ float ysh[64 * 65];

    const int nc = blockIdx.x;
    const int p  = blockIdx.y;
    const int h0 = p * 64;
    const int t  = threadIdx.x;
    const int ncY = (iter == 0) ? 0 : nc;

    #pragma unroll
    for (int k = 0; k < 16; ++k) {
        int idx = t + k * 256;
        int hh = idx >> 6, dc = idx & 63;
        Wsh[hh * 64 + dc] = W[(size_t)(h0 + hh) * (NCAP * NDIM) + nc * NDIM + dc];
    }
    #pragma unroll
    for (int k = 0; k < 16; ++k) {
        int idx = t + k * 256;
        int b = idx >> 6, hh = idx & 63;
        const float* yp = g_Y + (((size_t)b * NSPLIT) * NCAP + ncY) * NHID + h0 + hh;
        ysh[b * 65 + hh] = yp[0] + yp[NCAP * NHID] + yp[2 * NCAP * NHID] + yp[3 * NCAP * NHID];
    }
    __syncthreads();

    const int dc4  = (t & 15) * 4;
    const int brow = (t >> 4) * 4;
    float4 a0 = make_float4(0,0,0,0), a1 = a0, a2 = a0, a3 = a0;
    #pragma unroll 4
    for (int hh = 0; hh < 64; ++hh) {
        float4 w4 = *reinterpret_cast<const float4*>(&Wsh[hh * 64 + dc4]);
        fma4(a0, w4, ysh[(brow + 0) * 65 + hh]);
        fma4(a1, w4, ysh[(brow + 1) * 65 + hh]);
        fma4(a2, w4, ysh[(brow + 2) * 65 + hh]);
        fma4(a3, w4, ysh[(brow + 3) * 65 + hh]);
    }
    #pragma unroll
    for (int i = 0; i < 4; ++i) {
        float4 a = (i == 0) ? a0 : (i == 1) ? a1 : (i == 2) ? a2 : a3;
        *reinterpret_cast<float4*>(g_opart + (((size_t)p * NBATCH + brow + i) * NCAP + nc) * NDIM + dc4) = a;
    }
}

__global__ void __launch_bounds__(256)
squash_kernel(float* __restrict__ Og, int last) {
    const int b = blockIdx.x;
    const int t = threadIdx.x;
    const int nc = t >> 4;
    const int q  = t & 15;

    float4 a = make_float4(0,0,0,0);
    #pragma unroll
    for (int p = 0; p < NPART; ++p) {
        float4 v = *(reinterpret_cast<const float4*>(
            g_opart + (((size_t)p * NBATCH + b) * NCAP + nc) * NDIM) + q);
        a.x += v.x; a.y += v.y; a.z += v.z; a.w += v.w;
    }
    float ss = a.x * a.x + a.y * a.y + a.z * a.z + a.w * a.w;
    #pragma unroll
    for (int off = 8; off > 0; off >>= 1) ss += __shfl_xor_sync(0xffffffffu, ss, off);
    float inv = rsqrtf(ss + 1e-7f);
    a.x *= inv; a.y *= inv; a.z *= inv; a.w *= inv;

    *(reinterpret_cast<float4*>(g_O + ((size_t)b * NCAP + nc) * NDIM) + q) = a;
    if (last)
        *(reinterpret_cast<float4*>(Og + ((size_t)b * NCAP + nc) * NDIM) + q) = a;
}

// U2: V[b][nc][h0+hh] (+)= sum_dc W[h0+hh][nc*64+dc] * o[b][nc][dc], 64-h tiles.
__global__ void __launch_bounds__(256)
u2_kernel(const float* __restrict__ W, int iter) {
    __shared__ float WshT[64 * 68];  // [dc][hh], padded
    __shared__ float osh[64 * 64];   // [b][dc]

    const int nc = blockIdx.x;
    const int p  = blockIdx.y;
    const int h0 = p * 64;
    const int t  = threadIdx.x;

    #pragma unroll
    for (int k = 0; k < 16; ++k) {
        int idx = t + k * 256;
        int hh = idx >> 6, dc = idx & 63;
        WshT[dc * 68 + hh] = W[(size_t)(h0 + hh) * (NCAP * NDIM) + nc * NDIM + dc];
    }
    #pragma unroll
    for (int k = 0; k < 16; ++k) {
        int idx = t + k * 256;
        int b = idx >> 6, dc = idx & 63;
        osh[b * 64 + dc] = g_O[((size_t)b * NCAP + nc) * NDIM + dc];
    }
    __syncthreads();

    const int hh4  = (t & 15) * 4;
    const int brow = (t >> 4) * 4;
    float4 a0 = make_float4(0,0,0,0), a1 = a0, a2 = a0, a3 = a0;
    #pragma unroll 4
    for (int dc = 0; dc < 64; ++dc) {
        float4 w4 = *reinterpret_cast<const float4*>(&WshT[dc * 68 + hh4]);
        fma4(a0, w4, osh[(brow + 0) * 64 + dc]);
        fma4(a1, w4, osh[(brow + 1) * 64 + dc]);
        fma4(a2, w4, osh[(brow + 2) * 64 + dc]);
        fma4(a3, w4, osh[(brow + 3) * 64 + dc]);
    }
    #pragma unroll
    for (int i = 0; i < 4; ++i) {
        float4 a = (i == 0) ? a0 : (i == 1) ? a1 : (i == 2) ? a2 : a3;
        float4* vp = reinterpret_cast<float4*>(
            g_V + (((size_t)(brow + i)) * NCAP + nc) * NHID + h0 + hh4);
        if (iter == 0) {
            *vp = a;
        } else {
            float4 old = *vp;
            old.x += a.x; old.y += a.y; old.z += a.z; old.w += a.w;
            *vp = old;
        }
    }
}

extern "C" void kernel_launch(void* const* d_in, const int* in_sizes, int n_in,
                              void* d_out, int out_size) {
    (void)n_in; (void)out_size;
    const float* X = (const float*)d_in[0];
    const float* W = (const float*)d_in[1];
    if (in_sizes[0] == NHID * NCAP * NDIM) { const float* tmp = X; X = W; W = tmp; }

    cudaFuncSetAttribute(pass_kernel, cudaFuncAttributeMaxDynamicSharedMemorySize, 73728);

    float* out = (float*)d_out;
    for (int iter = 0; iter < 4; ++iter) {
        pass_kernel<<<dim3(NSPLIT, NBATCH), 256, 73728>>>(X, iter);
        u1_kernel<<<dim3(NCAP, NPART), 256>>>(W, iter);
        squash_kernel<<<NBATCH, 256>>>(out, iter == 3 ? 1 : 0);
        if (iter < 3) u2_kernel<<<dim3(NCAP, NPART), 256>>>(W, iter);
    }
}

// round 7
// speedup vs baseline: 1.7887x; 1.0410x over previous
#include <cuda_runtime.h>
#include <cuda_bf16.h>

#define NSEQ   512
#define NBATCH 64
#define NHID   1024
#define NCAP   16
#define NDIM   64
#define NSPLIT 4
#define SCHUNK 128   // NSEQ / NSPLIT
#define NPART  16

typedef unsigned uu;

// Scratch (device globals — no allocation allowed)
__device__ float g_V[NBATCH * NCAP * NHID];                  // 4 MB (fp32 master)
__device__ float g_Y[NBATCH * NSPLIT * NCAP * NHID];         // 16 MB
__device__ float g_opart[NPART * NBATCH * NCAP * NDIM];      // 4 MB
__device__ float g_O[NBATCH * NCAP * NDIM];                  // 256 KB
__device__ __nv_bfloat16 g_Xh[(size_t)NSEQ * NBATCH * NHID]; // 64 MB
__device__ __nv_bfloat16 g_Xl[(size_t)NSEQ * NBATCH * NHID]; // 64 MB
__device__ __nv_bfloat16 g_Vh[NBATCH * NCAP * NHID];         // 2 MB
__device__ __nv_bfloat16 g_Vl[NBATCH * NCAP * NHID];         // 2 MB

__device__ __forceinline__ void fma4(float4 &a, float4 x, float c) {
    a.x = fmaf(c, x.x, a.x);
    a.y = fmaf(c, x.y, a.y);
    a.z = fmaf(c, x.z, a.z);
    a.w = fmaf(c, x.w, a.w);
}

// ---- mma.sync / ldmatrix helpers (bf16 m16n8k16) ----
__device__ __forceinline__ uu su(const void* p) { return (uu)__cvta_generic_to_shared(p); }
__device__ __forceinline__ void ldm4(uu a, uu &r0, uu &r1, uu &r2, uu &r3) {
    asm volatile("ldmatrix.sync.aligned.m8n8.x4.shared.b16 {%0,%1,%2,%3},[%4];"
                 : "=r"(r0), "=r"(r1), "=r"(r2), "=r"(r3) : "r"(a));
}
__device__ __forceinline__ void ldm4t(uu a, uu &r0, uu &r1, uu &r2, uu &r3) {
    asm volatile("ldmatrix.sync.aligned.m8n8.x4.trans.shared.b16 {%0,%1,%2,%3},[%4];"
                 : "=r"(r0), "=r"(r1), "=r"(r2), "=r"(r3) : "r"(a));
}
__device__ __forceinline__ void ldm2(uu a, uu &r0, uu &r1) {
    asm volatile("ldmatrix.sync.aligned.m8n8.x2.shared.b16 {%0,%1},[%2];"
                 : "=r"(r0), "=r"(r1) : "r"(a));
}
__device__ __forceinline__ void mma16816(float* c, uu a0, uu a1, uu a2, uu a3, uu b0, uu b1) {
    asm volatile(
        "mma.sync.aligned.m16n8k16.row.col.f32.bf16.bf16.f32 "
        "{%0,%1,%2,%3},{%4,%5,%6,%7},{%8,%9},{%0,%1,%2,%3};"
        : "+f"(c[0]), "+f"(c[1]), "+f"(c[2]), "+f"(c[3])
        : "r"(a0), "r"(a1), "r"(a2), "r"(a3), "r"(b0), "r"(b1));
}

// ---- convert X (fp32) -> bf16 hi + lo residual, once per launch ----
__global__ void __launch_bounds__(256)
convert_kernel(const float* __restrict__ X) {
    const int base = blockIdx.x * 1024 + threadIdx.x;
    #pragma unroll
    for (int j = 0; j < 4; ++j) {
        const int i = base + j * 256;   // float4 index, 8388608 total
        float4 x = reinterpret_cast<const float4*>(X)[i];
        __nv_bfloat16 h0 = __float2bfloat16_rn(x.x);
        __nv_bfloat16 h1 = __float2bfloat16_rn(x.y);
        __nv_bfloat16 h2 = __float2bfloat16_rn(x.z);
        __nv_bfloat16 h3 = __float2bfloat16_rn(x.w);
        __nv_bfloat16 l0 = __float2bfloat16_rn(x.x - __bfloat162float(h0));
        __nv_bfloat16 l1 = __float2bfloat16_rn(x.y - __bfloat162float(h1));
        __nv_bfloat16 l2 = __float2bfloat16_rn(x.z - __bfloat162float(h2));
        __nv_bfloat16 l3 = __float2bfloat16_rn(x.w - __bfloat162float(h3));
        __nv_bfloat162 ph01 = __halves2bfloat162(h0, h1);
        __nv_bfloat162 ph23 = __halves2bfloat162(h2, h3);
        __nv_bfloat162 pl01 = __halves2bfloat162(l0, l1);
        __nv_bfloat162 pl23 = __halves2bfloat162(l2, l3);
        uint2 uh, ul;
        uh.x = reinterpret_cast<uu&>(ph01); uh.y = reinterpret_cast<uu&>(ph23);
        ul.x = reinterpret_cast<uu&>(pl01); ul.y = reinterpret_cast<uu&>(pl23);
        reinterpret_cast<uint2*>(g_Xh)[i] = uh;
        reinterpret_cast<uint2*>(g_Xl)[i] = ul;
    }
}

// SMEM layout (bytes), all 16B aligned:
#define SM_XH 0        // 128 x 136 bf16 = 34816
#define SM_XL 34816
#define SM_VH 69632    // 16 x 136 bf16 = 4352
#define SM_VL 73984
#define SM_L  78336    // 128 x 16 f32 = 8192
#define SM_CH 86528    // 16 x 136 bf16 (c^T hi)
#define SM_CL 90880
#define SM_TOTAL 95232
#define XSTR 136       // padded bf16 row stride

// ---------------------------------------------------------------------------
// pass_kernel (tensor): CTA = (split of 128 s, batch b), 256 thr / 8 warps.
// Stage A: L[128s x 16nc] = X · V^T  (bf16 hi/lo split, mma.sync)
// Softmax -> c^T[nc][s] bf16 hi/lo in smem.
// Stage B: per 128-h chunk, D[128h x 16nc] = X^T · C (ldmatrix.trans for X^T).
// iter==0: c = 1/16 exactly; scalar fp32 path, only nc=0 slice of Y written.
// ---------------------------------------------------------------------------
__global__ void __launch_bounds__(256)
pass_kernel(const float* __restrict__ X, int iter) {
    extern __shared__ char smraw[];
    __nv_bfloat16* smXh = reinterpret_cast<__nv_bfloat16*>(smraw + SM_XH);
    __nv_bfloat16* smXl = reinterpret_cast<__nv_bfloat16*>(smraw + SM_XL);
    __nv_bfloat16* smVh = reinterpret_cast<__nv_bfloat16*>(smraw + SM_VH);
    __nv_bfloat16* smVl = reinterpret_cast<__nv_bfloat16*>(smraw + SM_VL);
    float*         lsh  = reinterpret_cast<float*>(smraw + SM_L);
    __nv_bfloat16* smCh = reinterpret_cast<__nv_bfloat16*>(smraw + SM_CH);
    __nv_bfloat16* smCl = reinterpret_cast<__nv_bfloat16*>(smraw + SM_CL);

    const int b     = blockIdx.y;
    const int split = blockIdx.x;
    const int t     = threadIdx.x;
    const int lane  = t & 31;
    const int w     = t >> 5;
    const int s0    = split * SCHUNK;

    if (iter == 0) {
        // scalar streaming mean over s (exact: softmax of zeros = 1/16)
        const float4* X4 = reinterpret_cast<const float4*>(X);
        const float4* xb = X4 + ((size_t)s0 * NBATCH + b) * (NHID / 4) + t;
        const size_t xstride = (size_t)NBATCH * (NHID / 4);
        float4 a = make_float4(0.f, 0.f, 0.f, 0.f);
        #pragma unroll 8
        for (int s = 0; s < SCHUNK; ++s) {
            float4 x = xb[(size_t)s * xstride];
            a.x += x.x; a.y += x.y; a.z += x.z; a.w += x.w;
        }
        const float c = 1.0f / 16.0f;
        a.x *= c; a.y *= c; a.z *= c; a.w *= c;
        float4* Y4 = reinterpret_cast<float4*>(g_Y) + (size_t)(b * NSPLIT + split) * (NCAP * NHID / 4);
        Y4[t] = a;
        return;
    }

    // ============================ Stage A ============================
    float acc[6][4];   // [hh0,hh1,hl0,hl1,lh0,lh1][frag]
    #pragma unroll
    for (int i = 0; i < 6; ++i)
        #pragma unroll
        for (int k = 0; k < 4; ++k) acc[i][k] = 0.f;

    const uu sXh = su(smXh), sXl = su(smXl), sVh = su(smVh), sVl = su(smVl);
    // A (non-trans, row-major X[s][h]): s rows, k = h
    const uu aoffA = (uu)((w * 16 + (lane & 7) + ((lane >> 3) & 1) * 8) * (XSTR * 2) + (lane >> 4) * 16);
    // B (V rows [nc][h], k = h contiguous)
    const uu boffA = (uu)((lane & 7) * (XSTR * 2) + ((lane >> 3) & 1) * 16);

    for (int kc = 0; kc < 8; ++kc) {
        __syncthreads();
        #pragma unroll
        for (int r = 0; r < 8; ++r) {
            int idx = t + r * 256;
            int row = idx >> 4, c8 = idx & 15;
            size_t gb = ((size_t)(s0 + row) * NBATCH + b) * NHID + kc * 128;
            *reinterpret_cast<uint4*>(smXh + row * XSTR + c8 * 8) = reinterpret_cast<const uint4*>(g_Xh + gb)[c8];
            *reinterpret_cast<uint4*>(smXl + row * XSTR + c8 * 8) = reinterpret_cast<const uint4*>(g_Xl + gb)[c8];
        }
        {
            int row = t >> 4, c8 = t & 15;
            size_t vb = ((size_t)b * NCAP + row) * NHID + kc * 128;
            *reinterpret_cast<uint4*>(smVh + row * XSTR + c8 * 8) = reinterpret_cast<const uint4*>(g_Vh + vb)[c8];
            *reinterpret_cast<uint4*>(smVl + row * XSTR + c8 * 8) = reinterpret_cast<const uint4*>(g_Vl + vb)[c8];
        }
        __syncthreads();
        #pragma unroll
        for (int ks = 0; ks < 8; ++ks) {
            uu a0, a1, a2, a3, l0, l1, l2, l3;
            ldm4(sXh + aoffA + ks * 32, a0, a1, a2, a3);
            ldm4(sXl + aoffA + ks * 32, l0, l1, l2, l3);
            uu bh00, bh01, bh10, bh11, bl00, bl01, bl10, bl11;
            ldm2(sVh + boffA + ks * 32,                 bh00, bh01);
            ldm2(sVh + boffA + 8 * XSTR * 2 + ks * 32,  bh10, bh11);
            ldm2(sVl + boffA + ks * 32,                 bl00, bl01);
            ldm2(sVl + boffA + 8 * XSTR * 2 + ks * 32,  bl10, bl11);
            mma16816(acc[0], a0, a1, a2, a3, bh00, bh01);
            mma16816(acc[1], a0, a1, a2, a3, bh10, bh11);
            mma16816(acc[2], a0, a1, a2, a3, bl00, bl01);
            mma16816(acc[3], a0, a1, a2, a3, bl10, bl11);
            mma16816(acc[4], l0, l1, l2, l3, bh00, bh01);
            mma16816(acc[5], l0, l1, l2, l3, bh10, bh11);
        }
    }
    // write logits to lsh[s][nc]
    {
        const int m  = lane >> 2;
        const int n2 = (lane & 3) * 2;
        const int sr = w * 16 + m;
        float2 v;
        v.x = acc[0][0] + acc[2][0] + acc[4][0];
        v.y = acc[0][1] + acc[2][1] + acc[4][1];
        *reinterpret_cast<float2*>(&lsh[sr * 16 + n2]) = v;
        v.x = acc[0][2] + acc[2][2] + acc[4][2];
        v.y = acc[0][3] + acc[2][3] + acc[4][3];
        *reinterpret_cast<float2*>(&lsh[(sr + 8) * 16 + n2]) = v;
        v.x = acc[1][0] + acc[3][0] + acc[5][0];
        v.y = acc[1][1] + acc[3][1] + acc[5][1];
        *reinterpret_cast<float2*>(&lsh[sr * 16 + 8 + n2]) = v;
        v.x = acc[1][2] + acc[3][2] + acc[5][2];
        v.y = acc[1][3] + acc[3][3] + acc[5][3];
        *reinterpret_cast<float2*>(&lsh[(sr + 8) * 16 + 8 + n2]) = v;
    }
    __syncthreads();

    // softmax, write c^T[nc][s] as bf16 hi/lo
    if (t < SCHUNK) {
        float l[NCAP];
        #pragma unroll
        for (int i = 0; i < NCAP; ++i) l[i] = lsh[t * NCAP + i];
        float m = l[0];
        #pragma unroll
        for (int i = 1; i < NCAP; ++i) m = fmaxf(m, l[i]);
        float e[NCAP]; float ssum = 0.f;
        #pragma unroll
        for (int i = 0; i < NCAP; ++i) { e[i] = __expf(l[i] - m); ssum += e[i]; }
        float inv = 1.0f / ssum;
        #pragma unroll
        for (int i = 0; i < NCAP; ++i) {
            float c = e[i] * inv;
            __nv_bfloat16 ch = __float2bfloat16_rn(c);
            smCh[i * XSTR + t] = ch;
            smCl[i * XSTR + t] = __float2bfloat16_rn(c - __bfloat162float(ch));
        }
    }

    // ============================ Stage B ============================
    const uu sCh = su(smCh), sCl = su(smCl);
    // A^T via ldmatrix.trans on X[s][h]: k = s rows, m = h cols
    const uu aoffB = (uu)(((lane & 7) + (lane >> 4) * 8) * (XSTR * 2) + (w * 16 + ((lane >> 3) & 1) * 8) * 2);
    // B from c^T[nc][s]: k = s contiguous
    const uu boffB = (uu)((lane & 7) * (XSTR * 2) + ((lane >> 3) & 1) * 16);
    float* Yb = g_Y + (size_t)(b * NSPLIT + split) * NCAP * NHID;

    for (int kc = 0; kc < 8; ++kc) {
        __syncthreads();
        #pragma unroll
        for (int r = 0; r < 8; ++r) {
            int idx = t + r * 256;
            int row = idx >> 4, c8 = idx & 15;
            size_t gb = ((size_t)(s0 + row) * NBATCH + b) * NHID + kc * 128;
            *reinterpret_cast<uint4*>(smXh + row * XSTR + c8 * 8) = reinterpret_cast<const uint4*>(g_Xh + gb)[c8];
            *reinterpret_cast<uint4*>(smXl + row * XSTR + c8 * 8) = reinterpret_cast<const uint4*>(g_Xl + gb)[c8];
        }
        __syncthreads();

        float y[6][4];
        #pragma unroll
        for (int i = 0; i < 6; ++i)
            #pragma unroll
            for (int k = 0; k < 4; ++k) y[i][k] = 0.f;

        #pragma unroll
        for (int ks = 0; ks < 8; ++ks) {
            uu a0, a1, a2, a3, l0, l1, l2, l3;
            ldm4t(sXh + aoffB + ks * 16 * XSTR * 2, a0, a1, a2, a3);
            ldm4t(sXl + aoffB + ks * 16 * XSTR * 2, l0, l1, l2, l3);
            uu c00, c01, c10, c11, d00, d01, d10, d11;
            ldm2(sCh + boffB + ks * 32,                c00, c01);
            ldm2(sCh + boffB + 8 * XSTR * 2 + ks * 32, c10, c11);
            ldm2(sCl + boffB + ks * 32,                d00, d01);
            ldm2(sCl + boffB + 8 * XSTR * 2 + ks * 32, d10, d11);
            mma16816(y[0], a0, a1, a2, a3, c00, c01);
            mma16816(y[1], a0, a1, a2, a3, c10, c11);
            mma16816(y[2], a0, a1, a2, a3, d00, d01);
            mma16816(y[3], a0, a1, a2, a3, d10, d11);
            mma16816(y[4], l0, l1, l2, l3, c00, c01);
            mma16816(y[5], l0, l1, l2, l3, c10, c11);
        }
        // D[m=h][n=nc] -> g_Y[nc][h]
        const int m  = lane >> 2;
        const int n2 = (lane & 3) * 2;
        const int hg = kc * 128 + w * 16 + m;
        #pragma unroll
        for (int nt = 0; nt < 2; ++nt) {
            float y0 = y[nt][0] + y[2 + nt][0] + y[4 + nt][0];
            float y1 = y[nt][1] + y[2 + nt][1] + y[4 + nt][1];
            float y2 = y[nt][2] + y[2 + nt][2] + y[4 + nt][2];
            float y3 = y[nt][3] + y[2 + nt][3] + y[4 + nt][3];
            const int nc = nt * 8 + n2;
            Yb[(size_t)nc * NHID + hg]           = y0;
            Yb[(size_t)(nc + 1) * NHID + hg]     = y1;
            Yb[(size_t)nc * NHID + hg + 8]       = y2;
            Yb[(size_t)(nc + 1) * NHID + hg + 8] = y3;
        }
    }
}

// U1: opart[p][b][nc][dc] = sum_{hh in 64-part} (sum_splits Y) * W
__global__ void __launch_bounds__(256)
u1_kernel(const float* __restrict__ W, int iter) {
    __shared__ float Wsh[64 * 64];
    __shared__ float ysh[64 * 65];

    const int nc = blockIdx.x;
    const int p  = blockIdx.y;
    const int h0 = p * 64;
    const int t  = threadIdx.x;
    const int ncY = (iter == 0) ? 0 : nc;

    #pragma unroll
    for (int k = 0; k < 16; ++k) {
        int idx = t + k * 256;
        int hh = idx >> 6, dc = idx & 63;
        Wsh[hh * 64 + dc] = W[(size_t)(h0 + hh) * (NCAP * NDIM) + nc * NDIM + dc];
    }
    #pragma unroll
    for (int k = 0; k < 16; ++k) {
        int idx = t + k * 256;
        int b = idx >> 6, hh = idx & 63;
        const float* yp = g_Y + (((size_t)b * NSPLIT) * NCAP + ncY) * NHID + h0 + hh;
        ysh[b * 65 + hh] = yp[0] + yp[NCAP * NHID] + yp[2 * NCAP * NHID] + yp[3 * NCAP * NHID];
    }
    __syncthreads();

    const int dc4  = (t & 15) * 4;
    const int brow = (t >> 4) * 4;
    float4 a0 = make_float4(0,0,0,0), a1 = a0, a2 = a0, a3 = a0;
    #pragma unroll 4
    for (int hh = 0; hh < 64; ++hh) {
        float4 w4 = *reinterpret_cast<const float4*>(&Wsh[hh * 64 + dc4]);
        fma4(a0, w4, ysh[(brow + 0) * 65 + hh]);
        fma4(a1, w4, ysh[(brow + 1) * 65 + hh]);
        fma4(a2, w4, ysh[(brow + 2) * 65 + hh]);
        fma4(a3, w4, ysh[(brow + 3) * 65 + hh]);
    }
    #pragma unroll
    for (int i = 0; i < 4; ++i) {
        float4 a = (i == 0) ? a0 : (i == 1) ? a1 : (i == 2) ? a2 : a3;
        *reinterpret_cast<float4*>(g_opart + (((size_t)p * NBATCH + brow + i) * NCAP + nc) * NDIM + dc4) = a;
    }
}

__global__ void __launch_bounds__(256)
squash_kernel(float* __restrict__ Og, int last) {
    const int b = blockIdx.x;
    const int t = threadIdx.x;
    const int nc = t >> 4;
    const int q  = t & 15;

    float4 a = make_float4(0,0,0,0);
    #pragma unroll
    for (int p = 0; p < NPART; ++p) {
        float4 v = *(reinterpret_cast<const float4*>(
            g_opart + (((size_t)p * NBATCH + b) * NCAP + nc) * NDIM) + q);
        a.x += v.x; a.y += v.y; a.z += v.z; a.w += v.w;
    }
    float ss = a.x * a.x + a.y * a.y + a.z * a.z + a.w * a.w;
    #pragma unroll
    for (int off = 8; off > 0; off >>= 1) ss += __shfl_xor_sync(0xffffffffu, ss, off);
    float inv = rsqrtf(ss + 1e-7f);
    a.x *= inv; a.y *= inv; a.z *= inv; a.w *= inv;

    *(reinterpret_cast<float4*>(g_O + ((size_t)b * NCAP + nc) * NDIM) + q) = a;
    if (last)
        *(reinterpret_cast<float4*>(Og + ((size_t)b * NCAP + nc) * NDIM) + q) = a;
}

// U2: V (+)= W_nc @ o ; emits fp32 master + bf16 hi/lo copies for the tensor pass.
__global__ void __launch_bounds__(256)
u2_kernel(const float* __restrict__ W, int iter) {
    __shared__ float WshT[64 * 68];
    __shared__ float osh[64 * 64];

    const int nc = blockIdx.x;
    const int p  = blockIdx.y;
    const int h0 = p * 64;
    const int t  = threadIdx.x;

    #pragma unroll
    for (int k = 0; k < 16; ++k) {
        int idx = t + k * 256;
        int hh = idx >> 6, dc = idx & 63;
        WshT[dc * 68 + hh] = W[(size_t)(h0 + hh) * (NCAP * NDIM) + nc * NDIM + dc];
    }
    #pragma unroll
    for (int k = 0; k < 16; ++k) {
        int idx = t + k * 256;
        int b = idx >> 6, dc = idx & 63;
        osh[b * 64 + dc] = g_O[((size_t)b * NCAP + nc) * NDIM + dc];
    }
    __syncthreads();

    const int hh4  = (t & 15) * 4;
    const int brow = (t >> 4) * 4;
    float4 a0 = make_float4(0,0,0,0), a1 = a0, a2 = a0, a3 = a0;
    #pragma unroll 4
    for (int dc = 0; dc < 64; ++dc) {
        float4 w4 = *reinterpret_cast<const float4*>(&WshT[dc * 68 + hh4]);
        fma4(a0, w4, osh[(brow + 0) * 64 + dc]);
        fma4(a1, w4, osh[(brow + 1) * 64 + dc]);
        fma4(a2, w4, osh[(brow + 2) * 64 + dc]);
        fma4(a3, w4, osh[(brow + 3) * 64 + dc]);
    }
    #pragma unroll
    for (int i = 0; i < 4; ++i) {
        float4 a = (i == 0) ? a0 : (i == 1) ? a1 : (i == 2) ? a2 : a3;
        const size_t base = (((size_t)(brow + i)) * NCAP + nc) * NHID + h0 + hh4;
        float4* vp = reinterpret_cast<float4*>(g_V + base);
        float4 v;
        if (iter == 0) {
            v = a;
        } else {
            v = *vp;
            v.x += a.x; v.y += a.y; v.z += a.z; v.w += a.w;
        }
        *vp = v;
        // bf16 hi/lo copies
        __nv_bfloat16 h0b = __float2bfloat16_rn(v.x);
        __nv_bfloat16 h1b = __float2bfloat16_rn(v.y);
        __nv_bfloat16 h2b = __float2bfloat16_rn(v.z);
        __nv_bfloat16 h3b = __float2bfloat16_rn(v.w);
        __nv_bfloat16 l0b = __float2bfloat16_rn(v.x - __bfloat162float(h0b));
        __nv_bfloat16 l1b = __float2bfloat16_rn(v.y - __bfloat162float(h1b));
        __nv_bfloat16 l2b = __float2bfloat16_rn(v.z - __bfloat162float(h2b));
        __nv_bfloat16 l3b = __float2bfloat16_rn(v.w - __bfloat162float(h3b));
        __nv_bfloat162 ph01 = __halves2bfloat162(h0b, h1b);
        __nv_bfloat162 ph23 = __halves2bfloat162(h2b, h3b);
        __nv_bfloat162 pl01 = __halves2bfloat162(l0b, l1b);
        __nv_bfloat162 pl23 = __halves2bfloat162(l2b, l3b);
        uint2 uh, ul;
        uh.x = reinterpret_cast<uu&>(ph01); uh.y = reinterpret_cast<uu&>(ph23);
        ul.x = reinterpret_cast<uu&>(pl01); ul.y = reinterpret_cast<uu&>(pl23);
        *reinterpret_cast<uint2*>(g_Vh + base) = uh;
        *reinterpret_cast<uint2*>(g_Vl + base) = ul;
    }
}

extern "C" void kernel_launch(void* const* d_in, const int* in_sizes, int n_in,
                              void* d_out, int out_size) {
    (void)n_in; (void)out_size;
    const float* X = (const float*)d_in[0];
    const float* W = (const float*)d_in[1];
    if (in_sizes[0] == NHID * NCAP * NDIM) { const float* tmp = X; X = W; W = tmp; }

    cudaFuncSetAttribute(pass_kernel, cudaFuncAttributeMaxDynamicSharedMemorySize, SM_TOTAL);

    float* out = (float*)d_out;
    convert_kernel<<<8192, 256>>>(X);
    for (int iter = 0; iter < 4; ++iter) {
        pass_kernel<<<dim3(NSPLIT, NBATCH), 256, SM_TOTAL>>>(X, iter);
        u1_kernel<<<dim3(NCAP, NPART), 256>>>(W, iter);
        squash_kernel<<<NBATCH, 256>>>(out, iter == 3 ? 1 : 0);
        if (iter < 3) u2_kernel<<<dim3(NCAP, NPART), 256>>>(W, iter);
    }
}